// round 10
// baseline (speedup 1.0000x reference)
#include <cuda_runtime.h>
#include <cstdint>
#include <math.h>

// ---------------------------------------------------------------------------
// Compile-time stiffness coefficients (exact cofactor inverse of the 6x6
// compliance matrix, which is block-diagonal: asymmetric 3x3 block + 0.075*I).
// ---------------------------------------------------------------------------
constexpr double K_a = 1.0 / 0.21;          // 1/Ep
constexpr double K_b = 0.4 / 0.21;          // vp/Ep
constexpr double K_c = 0.4;                 // vp  (the asymmetry in row 2)
constexpr double K_A11 = K_a * K_a - K_b * K_c;
constexpr double K_DET = K_a * K_A11
                       - K_b * (K_b * (K_a + K_c))
                       - K_b * (K_c * (K_a + K_b));
constexpr float CM0  = (float)(K_A11 / K_DET);
constexpr float CM1  = (float)((K_b * (K_a + K_c)) / K_DET);
constexpr float CM23 = (float)(((K_b + K_c) * (K_a + K_b)) / K_DET);
constexpr float CM4  = (float)((K_a * K_a - K_b * K_b) / K_DET);
constexpr float CSH  = (float)((0.21 / 2.8) * 0.25);                // 0.075*0.25

// Pipeline geometry: 256 float4-groups (1024 points) per tile.
constexpr int G       = 256;
constexpr int UBYTES  = G * 48;                 // 12288 B per gradient array
constexpr int SBYTES  = G * 16;                 // 4096 B of sdf
constexpr int STAGE   = 3 * UBYTES + SBYTES;    // 40960 B
constexpr int NSTAGES = 2;
constexpr int SMEM_DYN = NSTAGES * STAGE;       // 81920 B

// Reduction state (zero at module load; finalizer restores zeros each call).
__device__ double       g_sum  = 0.0;
__device__ unsigned int g_cnt  = 0u;
__device__ unsigned int g_done = 0u;

__device__ __forceinline__ uint32_t smem_u32(const void* p) {
    return (uint32_t)__cvta_generic_to_shared(p);
}

__device__ __forceinline__ void accum_point(
    float ux, float uy, float uz,
    float vx, float vy, float vz,
    float wx, float wy, float wz,
    float sdf, float& acc, int& cnt)
{
    float e0 = ux, e1 = vy, e2 = wz;
    float s3 = uy + vx;
    float s4 = uz + wx;
    float s5 = wy + vz;
    float q = CM0 * (e0 * e0 + e1 * e1)
            + 2.0f * CM1 * (e0 * e1)
            + CM23 * ((e0 + e1) * e2)
            + CM4 * (e2 * e2)
            + CSH * (s3 * s3 + s4 * s4 + s5 * s5);
    if (sdf < 1e-8f) {
        acc += q * q;
        cnt += 1;
    }
}

__device__ __forceinline__ void accum_group(
    const float4& u0, const float4& u1, const float4& u2,
    const float4& v0, const float4& v1, const float4& v2,
    const float4& w0, const float4& w1, const float4& w2,
    const float4& s, float& acc, int& cnt)
{
    accum_point(u0.x, u0.y, u0.z, v0.x, v0.y, v0.z, w0.x, w0.y, w0.z, s.x, acc, cnt);
    accum_point(u0.w, u1.x, u1.y, v0.w, v1.x, v1.y, w0.w, w1.x, w1.y, s.y, acc, cnt);
    accum_point(u1.z, u1.w, u2.x, v1.z, v1.w, v2.x, w1.z, w1.w, w2.x, s.z, acc, cnt);
    accum_point(u2.y, u2.z, u2.w, v2.y, v2.z, v2.w, w2.y, w2.z, w2.w, s.w, acc, cnt);
}

__global__ void __launch_bounds__(256)
biomech_loss_kernel(const char* __restrict__ U,
                    const char* __restrict__ V,
                    const char* __restrict__ W,
                    const char* __restrict__ S,
                    float* __restrict__ out,
                    int ngroups, int n)
{
    extern __shared__ __align__(128) char dsm[];
    __shared__ __align__(8) uint64_t mbar[NSTAGES];

    const int tid = threadIdx.x;
    const int nfull = ngroups / G;

    if (tid == 0) {
        #pragma unroll
        for (int s = 0; s < NSTAGES; s++) {
            uint32_t mb = smem_u32(&mbar[s]);
            asm volatile("mbarrier.init.shared.b64 [%0], 1;" :: "r"(mb) : "memory");
        }
        asm volatile("fence.proxy.async.shared::cta;" ::: "memory");
    }
    __syncthreads();

    float acc = 0.0f;
    int   cnt = 0;
    int   ph[NSTAGES] = {0, 0};

    // ---- issue helper: bulk-copy one tile into a stage buffer -------------
    auto issue = [&](int stage, int tile) {
        uint32_t mb = smem_u32(&mbar[stage]);
        char* base = dsm + stage * STAGE;
        asm volatile("mbarrier.arrive.expect_tx.shared.b64 _, [%0], %1;"
                     :: "r"(mb), "r"((uint32_t)STAGE) : "memory");
        const char* su = U + (long)tile * UBYTES;
        const char* sv = V + (long)tile * UBYTES;
        const char* sw = W + (long)tile * UBYTES;
        const char* ss = S + (long)tile * SBYTES;
        asm volatile("cp.async.bulk.shared::cta.global.mbarrier::complete_tx::bytes [%0], [%1], %2, [%3];"
                     :: "r"(smem_u32(base)),              "l"(su), "r"((uint32_t)UBYTES), "r"(mb) : "memory");
        asm volatile("cp.async.bulk.shared::cta.global.mbarrier::complete_tx::bytes [%0], [%1], %2, [%3];"
                     :: "r"(smem_u32(base + UBYTES)),     "l"(sv), "r"((uint32_t)UBYTES), "r"(mb) : "memory");
        asm volatile("cp.async.bulk.shared::cta.global.mbarrier::complete_tx::bytes [%0], [%1], %2, [%3];"
                     :: "r"(smem_u32(base + 2 * UBYTES)), "l"(sw), "r"((uint32_t)UBYTES), "r"(mb) : "memory");
        asm volatile("cp.async.bulk.shared::cta.global.mbarrier::complete_tx::bytes [%0], [%1], %2, [%3];"
                     :: "r"(smem_u32(base + 3 * UBYTES)), "l"(ss), "r"((uint32_t)SBYTES), "r"(mb) : "memory");
    };

    // ---- prologue: prefetch first tile ------------------------------------
    const int tile0 = blockIdx.x;
    if (tid == 0 && tile0 < nfull) issue(0, tile0);

    // ---- pipelined main loop ----------------------------------------------
    int i = 0;
    for (int tile = tile0; tile < nfull; tile += gridDim.x, i++) {
        const int b = i & 1;
        const int nxt = tile + gridDim.x;
        if (tid == 0 && nxt < nfull) issue(b ^ 1, nxt);

        // Wait for this stage's copies (parity-phase, acquire).
        {
            uint32_t mb = smem_u32(&mbar[b]);
            uint32_t done = 0;
            while (!done) {
                asm volatile(
                    "{\n\t.reg .pred p;\n\t"
                    "mbarrier.try_wait.parity.acquire.cta.shared::cta.b64 p, [%1], %2, 0x989680;\n\t"
                    "selp.b32 %0, 1, 0, p;\n\t}"
                    : "=r"(done) : "r"(mb), "r"((uint32_t)ph[b]) : "memory");
            }
            ph[b] ^= 1;
        }

        // Compute: thread tid owns group tid of this tile (4 points).
        {
            const char* bb = dsm + b * STAGE;
            const float4* Ut = (const float4*)(bb);
            const float4* Vt = (const float4*)(bb + UBYTES);
            const float4* Wt = (const float4*)(bb + 2 * UBYTES);
            const float4* St = (const float4*)(bb + 3 * UBYTES);

            float4 u0 = Ut[3 * tid], u1 = Ut[3 * tid + 1], u2 = Ut[3 * tid + 2];
            float4 v0 = Vt[3 * tid], v1 = Vt[3 * tid + 1], v2 = Vt[3 * tid + 2];
            float4 w0 = Wt[3 * tid], w1 = Wt[3 * tid + 1], w2 = Wt[3 * tid + 2];
            float4 s  = St[tid];
            accum_group(u0, u1, u2, v0, v1, v2, w0, w1, w2, s, acc, cnt);
        }
        __syncthreads();   // everyone done reading before buffer reuse
    }

    // ---- remainder groups (ngroups % G) via direct loads, block 0 ---------
    if (blockIdx.x == 0) {
        const float4* Uf = (const float4*)U;
        const float4* Vf = (const float4*)V;
        const float4* Wf = (const float4*)W;
        const float4* Sf = (const float4*)S;
        for (int t = nfull * G + tid; t < ngroups; t += blockDim.x) {
            float4 s  = __ldcs(&Sf[t]);
            float4 u0 = __ldcs(&Uf[3 * t + 0]);
            float4 u1 = __ldcs(&Uf[3 * t + 1]);
            float4 u2 = __ldcs(&Uf[3 * t + 2]);
            float4 v0 = __ldcs(&Vf[3 * t + 0]);
            float4 v1 = __ldcs(&Vf[3 * t + 1]);
            float4 v2 = __ldcs(&Vf[3 * t + 2]);
            float4 w0 = __ldcs(&Wf[3 * t + 0]);
            float4 w1 = __ldcs(&Wf[3 * t + 1]);
            float4 w2 = __ldcs(&Wf[3 * t + 2]);
            accum_group(u0, u1, u2, v0, v1, v2, w0, w1, w2, s, acc, cnt);
        }
        // Scalar tail (n % 4) by one thread.
        if (tid == 0) {
            const float* gu = (const float*)U;
            const float* gv = (const float*)V;
            const float* gw = (const float*)W;
            const float* sd = (const float*)S;
            for (int p = 4 * ngroups; p < n; p++) {
                accum_point(gu[3 * p], gu[3 * p + 1], gu[3 * p + 2],
                            gv[3 * p], gv[3 * p + 1], gv[3 * p + 2],
                            gw[3 * p], gw[3 * p + 1], gw[3 * p + 2],
                            sd[p], acc, cnt);
            }
        }
    }

    // ---- reduction ---------------------------------------------------------
    #pragma unroll
    for (int o = 16; o > 0; o >>= 1) {
        acc += __shfl_down_sync(0xFFFFFFFFu, acc, o);
        cnt += __shfl_down_sync(0xFFFFFFFFu, cnt, o);
    }

    __shared__ float sacc[8];
    __shared__ int   scnt[8];
    int wid  = tid >> 5;
    int lane = tid & 31;
    if (lane == 0) { sacc[wid] = acc; scnt[wid] = cnt; }
    __syncthreads();

    if (wid == 0) {
        acc = (lane < 8) ? sacc[lane] : 0.0f;
        cnt = (lane < 8) ? scnt[lane] : 0;
        #pragma unroll
        for (int o = 4; o > 0; o >>= 1) {
            acc += __shfl_down_sync(0xFFFFFFFFu, acc, o);
            cnt += __shfl_down_sync(0xFFFFFFFFu, cnt, o);
        }
        if (lane == 0) {
            atomicAdd(&g_sum, (double)acc);
            atomicAdd(&g_cnt, (unsigned int)cnt);
            __threadfence();
            unsigned int ticket = atomicAdd(&g_done, 1u);
            if (ticket == gridDim.x - 1u) {
                double       total = atomicAdd(&g_sum, 0.0);
                unsigned int c     = atomicAdd(&g_cnt, 0u);
                out[0] = (float)(sqrt(total) / (double)c);
                g_sum  = 0.0;
                g_cnt  = 0u;
                g_done = 0u;
            }
        }
    }
}

extern "C" void kernel_launch(void* const* d_in, const int* in_sizes, int n_in,
                              void* d_out, int out_size)
{
    const char* gu = (const char*)d_in[0];
    const char* gv = (const char*)d_in[1];
    const char* gw = (const char*)d_in[2];
    const char* sd = (const char*)d_in[3];
    float* out = (float*)d_out;

    int n  = in_sizes[3];      // number of points
    int ng = n / 4;            // float4 groups
    int nfull = ng / G;        // full 256-group tiles

    static bool attr_set = false;
    if (!attr_set) {
        cudaFuncSetAttribute(biomech_loss_kernel,
                             cudaFuncAttributeMaxDynamicSharedMemorySize, SMEM_DYN);
        attr_set = true;
    }

    int nsm = 152;
    if (cudaDeviceGetAttribute(&nsm, cudaDevAttrMultiProcessorCount, 0)
        != cudaSuccess || nsm <= 0) {
        nsm = 152;
    }
    int blocks = 2 * nsm;                 // 2 CTAs/SM (80 KB smem each)
    if (blocks > nfull) blocks = (nfull > 0) ? nfull : 1;

    biomech_loss_kernel<<<blocks, 256, SMEM_DYN>>>(gu, gv, gw, sd, out, ng, n);
}